// round 9
// baseline (speedup 1.0000x reference)
#include <cuda_runtime.h>
#include <cstdint>

// ROI-align pooling R8: channel-sliced, bucket-sorted, persistent schedule.
//
// Bins sorted by anchor-pixel 8x8 tile (Morton, 256 buckets). Work unit =
// (sorted bin, channel slice of 256). W = slice*NBINS + sortedpos (closed
// form). SM r (= bid%148 residue class, deterministic classic-LUT placement,
// single wave) owns W in [r*TOT/148, (r+1)*TOT/148); its 8 co-resident
// blocks x 4 groups of 64 threads interleave stride-32, so the SM's live
// working set is one (bucket,slice) window: ~81 pixels x 1KB = 81KB <= L1.
// Redundant corner reads within the window hit L1 instead of L2 (the
// binding resource, ~10.2 TB/s achieved in R4).

#define POOL  7
#define NROIS 256
#define HH    128
#define WW    128
#define CC    1024
#define NBINS (NROIS * POOL * POOL)   // 12544
#define NSLICE 4
#define TOTW  (NBINS * NSLICE)        // 50176
#define NPB   1184                    // 148 SM x 8 blocks, single wave

__device__ int4           g_offs[NBINS];
__device__ float2         g_ts[NBINS];
__device__ unsigned char  g_key[NBINS];
__device__ int            g_hist[256];
__device__ int            g_base[256];
__device__ unsigned short g_order[NBINS];

__global__ void zero_kernel()
{
    g_hist[threadIdx.x] = 0;
}

__device__ __forceinline__ unsigned spread4(unsigned x)
{
    x = (x | (x << 2)) & 0x33u;
    x = (x | (x << 1)) & 0x55u;
    return x;
}

__global__ void setup_kernel(const float* __restrict__ rois)
{
    const int bin = blockIdx.x * blockDim.x + threadIdx.x;
    if (bin >= NBINS) return;

    const int roi = bin / (POOL * POOL);
    const int b49 = bin - roi * (POOL * POOL);
    const int iy  = b49 / POOL;
    const int ix  = b49 - iy * POOL;

    const float4 r = reinterpret_cast<const float4*>(rois)[roi];
    const int x0 = (int)(r.x * 0.0625f);
    const int y0 = (int)(r.y * 0.0625f);
    const int w  = (int)(r.z * 0.0625f);
    const int h  = (int)(r.w * 0.0625f);

    // identical fp32 math to reference
    const float sy = (float)iy * ((float)h / (float)POOL);
    const float sx = (float)ix * ((float)w / (float)POOL);
    const float fy = floorf(sy);
    const float fx = floorf(sx);
    const float ty = sy - fy;
    const float tx = sx - fx;

    const int y_lo = (int)fy;
    const int x_lo = (int)fx;
    const int y_hi = min(y_lo + 1, max(h - 1, 0));
    const int x_hi = min(x_lo + 1, max(w - 1, 0));

    const int gy0 = min(max(y0 + y_lo, 0), HH - 1);
    const int gy1 = min(max(y0 + y_hi, 0), HH - 1);
    const int gx0 = min(max(x0 + x_lo, 0), WW - 1);
    const int gx1 = min(max(x0 + x_hi, 0), WW - 1);

    // Fold dead-weight / clamp-identical hi corners onto lo corner (bit-exact).
    const int ex = (tx != 0.0f && gx1 != gx0) ? gx1 : gx0;
    const int ey = (ty != 0.0f && gy1 != gy0) ? gy1 : gy0;

    const int c4 = CC / 4;
    int4 o;
    o.x = (gy0 * WW + gx0) * c4;
    o.y = (gy0 * WW + ex ) * c4;
    o.z = (ey  * WW + gx0) * c4;
    o.w = (ey  * WW + ex ) * c4;
    g_offs[bin] = o;
    g_ts[bin]   = make_float2(tx, ty);

    // Morton key of anchor pixel's 8x8 tile -> 256 buckets.
    const unsigned kx = (unsigned)gx0 >> 3;
    const unsigned ky = (unsigned)gy0 >> 3;
    const unsigned char key = (unsigned char)((spread4(ky) << 1) | spread4(kx));
    g_key[bin] = key;
    atomicAdd(&g_hist[key], 1);
}

__global__ void scan_kernel()
{
    __shared__ int s[256];
    const int t = threadIdx.x;
    s[t] = g_hist[t];
    __syncthreads();
    int v = s[t];
    for (int d = 1; d < 256; d <<= 1) {
        int add = (t >= d) ? s[t - d] : 0;
        __syncthreads();
        s[t] = v = v + add;
        __syncthreads();
    }
    g_base[t] = v - g_hist[t];   // exclusive prefix
}

// Single-block scatter with SMEM cursors (global-atomic contention was 6.4us
// in R7; smem atomics make this ~1-2us).
__global__ void scatter_kernel()
{
    __shared__ int cur[256];
    const int t = threadIdx.x;
    if (t < 256) cur[t] = g_base[t];
    __syncthreads();
    for (int bin = t; bin < NBINS; bin += 1024) {
        const int k = g_key[bin];
        const int pos = atomicAdd(&cur[k], 1);
        g_order[pos] = (unsigned short)bin;
    }
}

__global__ __launch_bounds__(256, 8)
void roi_pool_kernel(const float* __restrict__ img,
                     float* __restrict__ out)
{
    const int t    = threadIdx.x;
    const int grp  = t >> 6;          // 0..3 (64-thread unit groups)
    const int lane = t & 63;          // float4 lane within a 256-ch slice

    const int rres = blockIdx.x % 148;    // SM residue class (co-resident set)
    const int j    = blockIdx.x / 148;    // 0..7 within the set

    const int lo = (int)((long long)rres       * TOTW / 148);
    const int hi = (int)((long long)(rres + 1) * TOTW / 148);

    const float4* __restrict__ imgv = reinterpret_cast<const float4*>(img);
    float4* __restrict__ outv = reinterpret_cast<float4*>(out);

    // 32 interleaved streams (8 blocks x 4 groups) sweep the SM's W-range
    // together: the live window is one (bucket, slice) at a time.
    for (int W = lo + (grp << 3) + j; W < hi; W += 32) {
        const int s   = W / NBINS;          // slice 0..3
        const int pos = W - s * NBINS;
        const int bin = g_order[pos];

        const int4   o  = g_offs[bin];
        const float2 tw = g_ts[bin];
        const float  tx = tw.x, ty = tw.y;

        const int ch = (s << 6) + lane;     // float4 index 0..255 in pixel

        const float4 a = imgv[o.x + ch];
        const float4 b = imgv[o.y + ch];
        const float4 c = imgv[o.z + ch];
        const float4 d = imgv[o.w + ch];

        float4 r;
        {
            float top, bot;
            top = a.x + tx * (b.x - a.x);
            bot = c.x + tx * (d.x - c.x);
            r.x = top + ty * (bot - top);
            top = a.y + tx * (b.y - a.y);
            bot = c.y + tx * (d.y - c.y);
            r.y = top + ty * (bot - top);
            top = a.z + tx * (b.z - a.z);
            bot = c.z + tx * (d.z - c.z);
            r.z = top + ty * (bot - top);
            top = a.w + tx * (b.w - a.w);
            bot = c.w + tx * (d.w - c.w);
            r.w = top + ty * (bot - top);
        }
        outv[(size_t)bin * (CC / 4) + ch] = r;
    }
}

extern "C" void kernel_launch(void* const* d_in, const int* in_sizes, int n_in,
                              void* d_out, int out_size)
{
    const float* img  = (const float*)d_in[0];
    const float* rois = (const float*)d_in[1];
    if (n_in >= 2 && in_sizes[0] < in_sizes[1]) {
        img  = (const float*)d_in[1];
        rois = (const float*)d_in[0];
    }
    float* out = (float*)d_out;

    zero_kernel<<<1, 256>>>();
    setup_kernel<<<(NBINS + 255) / 256, 256>>>(rois);
    scan_kernel<<<1, 256>>>();
    scatter_kernel<<<1, 1024>>>();
    roi_pool_kernel<<<NPB, 256>>>(img, out);
}

// round 10
// speedup vs baseline: 1.1525x; 1.1525x over previous
#include <cuda_runtime.h>
#include <cstdint>

// ROI-align pooling R9: ROI-bucketed persistent schedule, NO sorting.
// img (1,128,128,1024) NHWC fp32, rois (1,256,4), out (1,256,7,7,1024) fp32.
//
// Intra-ROI corner redundancy (~196 corner reads over ~40-64 unique pixels
// per ROI) is captured in L1 by making the ROI the scheduling bucket:
// block = (roi, half): owns all 49 bins x 2 channel slices of 256.
// Slices run sequentially -> live working set = one slice of the ROI's
// unique pixels (~64KB); ~3.5 co-resident blocks ~= L1 capacity.
// 4 groups of 64 threads stride the bins. Per-bin setup precomputed by the
// cheap setup_kernel (R4 style, ~0.4us); all sort machinery removed.

#define POOL  7
#define NROIS 256
#define HH    128
#define WW    128
#define CC    1024
#define NBINS (NROIS * POOL * POOL)   // 12544

__device__ int4   g_offs[NBINS];
__device__ float2 g_ts[NBINS];

__global__ void setup_kernel(const float* __restrict__ rois)
{
    const int bin = blockIdx.x * blockDim.x + threadIdx.x;
    if (bin >= NBINS) return;

    const int roi = bin / (POOL * POOL);
    const int b49 = bin - roi * (POOL * POOL);
    const int iy  = b49 / POOL;
    const int ix  = b49 - iy * POOL;

    const float4 r = reinterpret_cast<const float4*>(rois)[roi];
    const int x0 = (int)(r.x * 0.0625f);
    const int y0 = (int)(r.y * 0.0625f);
    const int w  = (int)(r.z * 0.0625f);
    const int h  = (int)(r.w * 0.0625f);

    // identical fp32 math to reference
    const float sy = (float)iy * ((float)h / (float)POOL);
    const float sx = (float)ix * ((float)w / (float)POOL);
    const float fy = floorf(sy);
    const float fx = floorf(sx);
    const float ty = sy - fy;
    const float tx = sx - fx;

    const int y_lo = (int)fy;
    const int x_lo = (int)fx;
    const int y_hi = min(y_lo + 1, max(h - 1, 0));
    const int x_hi = min(x_lo + 1, max(w - 1, 0));

    const int gy0 = min(max(y0 + y_lo, 0), HH - 1);
    const int gy1 = min(max(y0 + y_hi, 0), HH - 1);
    const int gx0 = min(max(x0 + x_lo, 0), WW - 1);
    const int gx1 = min(max(x0 + x_hi, 0), WW - 1);

    // Fold dead-weight (weight==0) / clamp-identical hi corners onto the lo
    // corner (bit-exact) - removes dead L2 traffic and shrinks the unique-
    // pixel working set.
    const int ex = (tx != 0.0f && gx1 != gx0) ? gx1 : gx0;
    const int ey = (ty != 0.0f && gy1 != gy0) ? gy1 : gy0;

    const int c4 = CC / 4;
    int4 o;
    o.x = (gy0 * WW + gx0) * c4;
    o.y = (gy0 * WW + ex ) * c4;
    o.z = (ey  * WW + gx0) * c4;
    o.w = (ey  * WW + ex ) * c4;
    g_offs[bin] = o;
    g_ts[bin]   = make_float2(tx, ty);
}

__global__ __launch_bounds__(256, 8)
void roi_pool_kernel(const float* __restrict__ img,
                     float* __restrict__ out)
{
    const int t    = threadIdx.x;
    const int grp  = t >> 6;              // 0..3: bin group
    const int lane = t & 63;              // float4 lane within a 256-ch slice

    const int roi  = blockIdx.x >> 1;     // 0..255
    const int half = blockIdx.x & 1;      // slices {2*half, 2*half+1}

    const float4* __restrict__ imgv = reinterpret_cast<const float4*>(img);
    float4* __restrict__ outv = reinterpret_cast<float4*>(out);

    const int binbase = roi * (POOL * POOL);

    #pragma unroll
    for (int si = 0; si < 2; si++) {
        const int s  = half * 2 + si;     // slice 0..3
        const int ch = (s << 6) + lane;   // float4 index 0..255 within pixel

        // 4 groups sweep the 49 bins of this ROI for slice s; all reads
        // land in the ROI's unique-pixel set for this slice (~64KB -> L1).
        for (int b = grp; b < POOL * POOL; b += 4) {
            const int bin = binbase + b;

            const int4   o  = g_offs[bin];
            const float2 tw = g_ts[bin];
            const float  tx = tw.x, ty = tw.y;

            const float4 a = imgv[o.x + ch];
            const float4 bb = imgv[o.y + ch];
            const float4 c = imgv[o.z + ch];
            const float4 d = imgv[o.w + ch];

            float4 r;
            {
                float top, bot;
                top = a.x + tx * (bb.x - a.x);
                bot = c.x + tx * (d.x - c.x);
                r.x = top + ty * (bot - top);
                top = a.y + tx * (bb.y - a.y);
                bot = c.y + tx * (d.y - c.y);
                r.y = top + ty * (bot - top);
                top = a.z + tx * (bb.z - a.z);
                bot = c.z + tx * (d.z - c.z);
                r.z = top + ty * (bot - top);
                top = a.w + tx * (bb.w - a.w);
                bot = c.w + tx * (d.w - c.w);
                r.w = top + ty * (bot - top);
            }
            outv[(size_t)bin * (CC / 4) + ch] = r;
        }
    }
}

extern "C" void kernel_launch(void* const* d_in, const int* in_sizes, int n_in,
                              void* d_out, int out_size)
{
    const float* img  = (const float*)d_in[0];
    const float* rois = (const float*)d_in[1];
    if (n_in >= 2 && in_sizes[0] < in_sizes[1]) {
        img  = (const float*)d_in[1];
        rois = (const float*)d_in[0];
    }
    float* out = (float*)d_out;

    setup_kernel<<<(NBINS + 255) / 256, 256>>>(rois);
    roi_pool_kernel<<<NROIS * 2, 256>>>(img, out);
}

// round 14
// speedup vs baseline: 1.6782x; 1.4562x over previous
#include <cuda_runtime.h>
#include <cstdint>

// ROI-align pooling R10: dual-bin interleaved blocks for 2x MLP.
// img (1,128,128,1024) NHWC fp32, rois (1,256,4), out (1,256,7,7,1024) fp32.
//
// Diagnosis so far: no resource saturated (DRAM 38%, L2 35%, L1 48%, issue
// 26%) and time is invariant to L2 traffic (R1 vs R3) -> latency
// equilibrium, bound by the per-warp chain params->4 loads->fma->store with
// only 4 loads in flight. Fix: each block computes TWO independent bins
// (b, b+6272); their param loads and 8 corner loads are all independent and
// front-batched -> MLP_p1 = 8 at ~5 blocks/SM occupancy. Unlike R5 there is
// NO serial prefetch chain and no persistence.

#define POOL  7
#define NROIS 256
#define HH    128
#define WW    128
#define CC    1024
#define NBINS (NROIS * POOL * POOL)   // 12544
#define HALF  (NBINS / 2)             // 6272

__device__ int4   g_offs[NBINS];
__device__ float2 g_ts[NBINS];

__global__ void setup_kernel(const float* __restrict__ rois)
{
    const int bin = blockIdx.x * blockDim.x + threadIdx.x;
    if (bin >= NBINS) return;

    const int roi = bin / (POOL * POOL);
    const int b49 = bin - roi * (POOL * POOL);
    const int iy  = b49 / POOL;
    const int ix  = b49 - iy * POOL;

    const float4 r = reinterpret_cast<const float4*>(rois)[roi];
    const int x0 = (int)(r.x * 0.0625f);
    const int y0 = (int)(r.y * 0.0625f);
    const int w  = (int)(r.z * 0.0625f);
    const int h  = (int)(r.w * 0.0625f);

    // identical fp32 math to reference
    const float sy = (float)iy * ((float)h / (float)POOL);
    const float sx = (float)ix * ((float)w / (float)POOL);
    const float fy = floorf(sy);
    const float fx = floorf(sx);
    const float ty = sy - fy;
    const float tx = sx - fx;

    const int y_lo = (int)fy;
    const int x_lo = (int)fx;
    const int y_hi = min(y_lo + 1, max(h - 1, 0));
    const int x_hi = min(x_lo + 1, max(w - 1, 0));

    const int gy0 = min(max(y0 + y_lo, 0), HH - 1);
    const int gy1 = min(max(y0 + y_hi, 0), HH - 1);
    const int gx0 = min(max(x0 + x_lo, 0), WW - 1);
    const int gx1 = min(max(x0 + x_hi, 0), WW - 1);

    // Fold dead-weight / clamp-identical hi corners onto lo corner (bit-exact).
    const int ex = (tx != 0.0f && gx1 != gx0) ? gx1 : gx0;
    const int ey = (ty != 0.0f && gy1 != gy0) ? gy1 : gy0;

    const int c4 = CC / 4;
    int4 o;
    o.x = (gy0 * WW + gx0) * c4;
    o.y = (gy0 * WW + ex ) * c4;
    o.z = (ey  * WW + gx0) * c4;
    o.w = (ey  * WW + ex ) * c4;
    g_offs[bin] = o;
    g_ts[bin]   = make_float2(tx, ty);
}

__device__ __forceinline__ float4 lerp2(float4 a, float4 b, float4 c, float4 d,
                                        float tx, float ty)
{
    float4 r;
    float top, bot;
    top = a.x + tx * (b.x - a.x);
    bot = c.x + tx * (d.x - c.x);
    r.x = top + ty * (bot - top);
    top = a.y + tx * (b.y - a.y);
    bot = c.y + tx * (d.y - c.y);
    r.y = top + ty * (bot - top);
    top = a.z + tx * (b.z - a.z);
    bot = c.z + tx * (d.z - c.z);
    r.z = top + ty * (bot - top);
    top = a.w + tx * (b.w - a.w);
    bot = c.w + tx * (d.w - c.w);
    r.w = top + ty * (bot - top);
    return r;
}

__global__ __launch_bounds__(256)
void roi_pool_kernel(const float* __restrict__ img,
                     float* __restrict__ out)
{
    const int t    = threadIdx.x;       // 0..255: one float4 lane
    const int bin0 = blockIdx.x;        // 0..6271
    const int bin1 = bin0 + HALF;       // 6272..12543

    const float4* __restrict__ imgv = reinterpret_cast<const float4*>(img);
    float4* __restrict__ outv = reinterpret_cast<float4*>(out);

    // Two independent param fetches (issue back-to-back).
    const int4   o0  = g_offs[bin0];
    const int4   o1  = g_offs[bin1];
    const float2 tw0 = g_ts[bin0];
    const float2 tw1 = g_ts[bin1];

    // 8 independent, front-batched corner loads: MLP_p1 = 8.
    const float4 a0 = imgv[o0.x + t];
    const float4 b0 = imgv[o0.y + t];
    const float4 c0 = imgv[o0.z + t];
    const float4 d0 = imgv[o0.w + t];
    const float4 a1 = imgv[o1.x + t];
    const float4 b1 = imgv[o1.y + t];
    const float4 c1 = imgv[o1.z + t];
    const float4 d1 = imgv[o1.w + t];

    const float4 r0 = lerp2(a0, b0, c0, d0, tw0.x, tw0.y);
    outv[(size_t)bin0 * (CC / 4) + t] = r0;

    const float4 r1 = lerp2(a1, b1, c1, d1, tw1.x, tw1.y);
    outv[(size_t)bin1 * (CC / 4) + t] = r1;
}

extern "C" void kernel_launch(void* const* d_in, const int* in_sizes, int n_in,
                              void* d_out, int out_size)
{
    const float* img  = (const float*)d_in[0];
    const float* rois = (const float*)d_in[1];
    if (n_in >= 2 && in_sizes[0] < in_sizes[1]) {
        img  = (const float*)d_in[1];
        rois = (const float*)d_in[0];
    }
    float* out = (float*)d_out;

    setup_kernel<<<(NBINS + 255) / 256, 256>>>(rois);
    roi_pool_kernel<<<HALF, 256>>>(img, out);
}